// round 2
// baseline (speedup 1.0000x reference)
#include <cuda_runtime.h>

// Problem shape (fixed by setup_inputs)
#define BQ 4
#define TT 96
#define NN 512
#define ROW_LEN 514              // [beta_logit, gamma_logit, z_0..z_511]
#define EPSV 1e-8f

// Scratch (no allocations allowed): ping-pong SIR state + per-(b,t) arrival counters
__device__ float g_x[2][BQ][NN][3];
__device__ unsigned g_arrive[BQ * TT];

// ---------------------------------------------------------------------------
// Reset barrier counters (must be re-zeroed every launch; graph-capturable)
// ---------------------------------------------------------------------------
__global__ void reset_kernel() {
    g_arrive[threadIdx.x] = 0u;
}

// ---------------------------------------------------------------------------
// Kernel A: epiparams = [sigmoid(p0), sigmoid(p1), softmax(p2..p513)]
// One warp per row; lane j handles elements j, j+32, ..., j+480 of z.
// Pure streaming: 404 MB read + 406 MB write.
// ---------------------------------------------------------------------------
__global__ __launch_bounds__(256) void epi_kernel(const float* __restrict__ params,
                                                  float* __restrict__ epi) {
    const int gw   = (blockIdx.x * 256 + threadIdx.x) >> 5;  // global warp = row
    const int lane = threadIdx.x & 31;
    const float* p = params + (size_t)gw * ROW_LEN;
    float*       o = epi    + (size_t)gw * ROW_LEN;

    float v[16];
    float mx = -3.4e38f;
#pragma unroll
    for (int k = 0; k < 16; k++) {
        v[k] = p[2 + lane + 32 * k];
        mx = fmaxf(mx, v[k]);
    }
#pragma unroll
    for (int off = 16; off; off >>= 1)
        mx = fmaxf(mx, __shfl_xor_sync(0xffffffffu, mx, off));

    float s = 0.f;
#pragma unroll
    for (int k = 0; k < 16; k++) {
        v[k] = __expf(v[k] - mx);
        s += v[k];
    }
#pragma unroll
    for (int off = 16; off; off >>= 1)
        s += __shfl_xor_sync(0xffffffffu, s, off);

    const float inv = 1.0f / s;

    if (lane < 2)
        o[lane] = 1.0f / (1.0f + __expf(-p[lane]));
#pragma unroll
    for (int k = 0; k < 16; k++)
        o[2 + lane + 32 * k] = v[k] * inv;
}

// ---------------------------------------------------------------------------
// Kernel B: sequential SIR scan. 128 persistent co-resident blocks:
//   block -> batch b = bid>>5, rows [ (bid&31)*16 , +16 ).
// Per step: load I vector to smem, warp-per-row dot(c_row, I), elementwise
// update, write output_view + ping-pong state, then a 32-block per-batch
// software barrier (atomic arrive + volatile spin).
// Cross-block visibility: __threadfence (gpu scope -> L1D flush on sm_103a)
// around the barrier, __ldcg for state reads (L2, bypass L1).
// ---------------------------------------------------------------------------
__global__ __launch_bounds__(256) void scan_kernel(const float* __restrict__ x0,
                                                   const float* __restrict__ epi,
                                                   float* __restrict__ out_view) {
    const int b       = blockIdx.x >> 5;          // 32 blocks per batch
    const int rowBase = (blockIdx.x & 31) << 4;   // 16 rows per block
    const int tid  = threadIdx.x;
    const int lane = tid & 31;
    const int wid  = tid >> 5;                    // 8 warps

    __shared__ float I_sh[NN];

    for (int t = 0; t < TT; t++) {
        // ---- load I_{t-1} for this batch into shared ----
        if (t == 0) {
            for (int i = tid; i < NN; i += 256)
                I_sh[i] = x0[(b * NN + i) * 3 + 1];
        } else {
            const float* xs = &g_x[t & 1][b][0][0];
            for (int i = tid; i < NN; i += 256)
                I_sh[i] = __ldcg(xs + i * 3 + 1);
        }
        __syncthreads();

        const float* eb = epi + ((size_t)(b * TT + t) * NN) * ROW_LEN;

#pragma unroll
        for (int r = 0; r < 2; r++) {
            const int row = rowBase + wid + (r << 3);
            const float* crow = eb + (size_t)row * ROW_LEN;

            float acc = 0.f;
#pragma unroll
            for (int k = 0; k < 16; k++) {
                const int j = lane + 32 * k;
                acc = fmaf(crow[2 + j], I_sh[j], acc);
            }
#pragma unroll
            for (int off = 16; off; off >>= 1)
                acc += __shfl_xor_sync(0xffffffffu, acc, off);

            if (lane == 0) {
                const float beta  = crow[0];
                const float gamma = crow[1];
                float S, I, R;
                if (t == 0) {
                    const float* xr = x0 + (size_t)(b * NN + row) * 3;
                    S = xr[0]; I = xr[1]; R = xr[2];
                } else {
                    const float* xr = &g_x[t & 1][b][row][0];
                    S = __ldcg(xr); I = __ldcg(xr + 1); R = __ldcg(xr + 2);
                }
                const float Np = fmaxf(S + I + R, EPSV);
                const float dS = -(beta * S * acc) / Np;
                const float dR = gamma * I;
                const float dI = -dS - dR;
                float St = fmaxf(S + dS, 0.f);
                float It = fmaxf(I + dI, 0.f);
                float Rt = fmaxf(R + dR, 0.f);
                const float scale = Np / fmaxf(St + It + Rt, EPSV);
                St *= scale; It *= scale; Rt *= scale;

                float* xn = &g_x[(t + 1) & 1][b][row][0];
                xn[0] = St; xn[1] = It; xn[2] = Rt;

                const size_t ov = ((size_t)(b * TT + t) * NN + row) * 3;
                out_view[ov]     = St;
                out_view[ov + 1] = It;
                out_view[ov + 2] = Rt;
            }
        }

        __syncthreads();
        if (t < TT - 1) {
            if (tid == 0) {
                __threadfence();                       // publish x_new (release)
                atomicAdd(&g_arrive[b * TT + t], 1u);
                volatile unsigned* vf = g_arrive + b * TT + t;
                while (*vf < 32u) { }
                __threadfence();                       // acquire
            }
            __syncthreads();
        }
    }
}

// ---------------------------------------------------------------------------
// Launch
// ---------------------------------------------------------------------------
extern "C" void kernel_launch(void* const* d_in, const int* in_sizes, int n_in,
                              void* d_out, int out_size) {
    // metadata order: x0 (B*N*3 = 6144), params (B*T*N*514). Be robust anyway.
    const float* x0;
    const float* params;
    if (in_sizes[0] == BQ * NN * 3) {
        x0     = (const float*)d_in[0];
        params = (const float*)d_in[1];
    } else {
        x0     = (const float*)d_in[1];
        params = (const float*)d_in[0];
    }

    float* out      = (float*)d_out;
    float* out_view = out;                                  // (B,T,N,3)
    float* epi      = out + (size_t)BQ * TT * NN * 3;       // (B,T,N,514)

    reset_kernel<<<1, BQ * TT>>>();

    const int nrows = BQ * TT * NN;                         // 196608 rows
    epi_kernel<<<nrows / 8, 256>>>(params, epi);            // 8 warps/block

    scan_kernel<<<128, 256>>>(x0, epi, out_view);
}

// round 3
// speedup vs baseline: 1.6324x; 1.6324x over previous
#include <cuda_runtime.h>

// Problem shape (fixed by setup_inputs)
#define BQ 4
#define TT 96
#define NN 512
#define ROW_LEN 514              // [beta_logit, gamma_logit, z_0..z_511]
#define EPSV 1e-8f
#define BLOCKS_PER_BATCH 64      // 64 blocks x 8 warps = 512 rows per batch

// Scratch (allocations forbidden): ping-pong SIR state, contiguous I vector,
// and per-(b,t) barrier arrival counters.
__device__ float    g_x[2][BQ][NN][3];
__device__ float    g_I[2][BQ][NN];
__device__ unsigned g_arrive[BQ * TT];

// ---------------------------------------------------------------------------
// Reset barrier counters (graph replays reuse device globals)
// ---------------------------------------------------------------------------
__global__ void reset_kernel() {
    g_arrive[threadIdx.x] = 0u;
}

// ---------------------------------------------------------------------------
// Fused kernel: per step t, each warp owns one row (b, t, n):
//   1) sigmoid/softmax of its params row  -> epi output, c-row kept in regs
//   2) wait per-batch barrier for step t-1 (hidden behind phase 1 streaming)
//   3) infection = dot(c_row_regs, I_sh); SIR update; write out_view + state
//   4) release-fence + arrive
// 256 persistent blocks (all co-resident: 148 SMs x 8 blocks capacity).
// Cross-block state reads use __ldcg (L1 is not coherent on sm_103a).
// ---------------------------------------------------------------------------
__global__ __launch_bounds__(256, 1)
void fused_kernel(const float* __restrict__ x0,
                  const float* __restrict__ params,
                  float* __restrict__ out_view,
                  float* __restrict__ epi) {
    const int b    = blockIdx.x >> 6;            // batch
    const int loc  = blockIdx.x & 63;            // block within batch
    const int tid  = threadIdx.x;
    const int lane = tid & 31;
    const int wid  = tid >> 5;                   // 8 warps
    const int row  = loc * 8 + wid;              // node index this warp owns

    __shared__ float I_sh[NN];

    for (int t = 0; t < TT; t++) {
        // ---------- phase 1: sigmoid + softmax (independent of scan state) ----------
        const size_t rbase = ((size_t)(b * TT + t) * NN + row) * ROW_LEN;
        const float* p = params + rbase;
        float*       o = epi    + rbase;

        float v[16];
        float mx = -3.4e38f;
#pragma unroll
        for (int k = 0; k < 16; k++) {
            v[k] = __ldcs(p + 2 + lane + 32 * k);
            mx = fmaxf(mx, v[k]);
        }
#pragma unroll
        for (int off = 16; off; off >>= 1)
            mx = fmaxf(mx, __shfl_xor_sync(0xffffffffu, mx, off));

        float s = 0.f;
#pragma unroll
        for (int k = 0; k < 16; k++) {
            v[k] = __expf(v[k] - mx);
            s += v[k];
        }
#pragma unroll
        for (int off = 16; off; off >>= 1)
            s += __shfl_xor_sync(0xffffffffu, s, off);
        const float inv = 1.0f / s;

        float bg = 0.f;                           // lane0: beta, lane1: gamma
        if (lane < 2) {
            bg = 1.0f / (1.0f + __expf(-__ldcs(p + lane)));
            __stcs(o + lane, bg);
        }
#pragma unroll
        for (int k = 0; k < 16; k++) {
            v[k] *= inv;                          // c-row stays in registers
            __stcs(o + 2 + lane + 32 * k, v[k]);
        }

        // ---------- phase 2: wait for step t-1 (overlaps stragglers w/ phase 1) ----------
        if (t > 0) {
            if (tid == 0) {
                volatile unsigned* vf = g_arrive + (b * TT + t - 1);
                while (*vf < BLOCKS_PER_BATCH) { }
                __threadfence();                  // acquire
            }
            __syncthreads();                      // also guards I_sh reuse
        }

        // ---------- load I_{t-1} for this batch into shared ----------
        if (t == 0) {
            for (int i = tid; i < NN; i += 256)
                I_sh[i] = x0[(b * NN + i) * 3 + 1];
        } else {
            const float* Ij = &g_I[t & 1][b][0];
            for (int i = tid; i < NN; i += 256)
                I_sh[i] = __ldcg(Ij + i);
        }
        __syncthreads();

        // ---------- phase 3: infection dot from registers + SIR update ----------
        float acc = 0.f;
#pragma unroll
        for (int k = 0; k < 16; k++)
            acc = fmaf(v[k], I_sh[lane + 32 * k], acc);
#pragma unroll
        for (int off = 16; off; off >>= 1)
            acc += __shfl_xor_sync(0xffffffffu, acc, off);

        const float gamma = __shfl_sync(0xffffffffu, bg, 1);

        if (lane == 0) {
            const float beta = bg;
            float S, I, R;
            if (t == 0) {
                const float* xr = x0 + (size_t)(b * NN + row) * 3;
                S = xr[0]; I = xr[1]; R = xr[2];
            } else {
                const float* xr = &g_x[t & 1][b][row][0];
                S = __ldcg(xr); I = __ldcg(xr + 1); R = __ldcg(xr + 2);
            }
            const float Np = fmaxf(S + I + R, EPSV);
            const float dS = -(beta * S * acc) / Np;
            const float dR = gamma * I;
            const float dI = -dS - dR;
            float St = fmaxf(S + dS, 0.f);
            float It = fmaxf(I + dI, 0.f);
            float Rt = fmaxf(R + dR, 0.f);
            const float scale = Np / fmaxf(St + It + Rt, EPSV);
            St *= scale; It *= scale; Rt *= scale;

            float* xn = &g_x[(t + 1) & 1][b][row][0];
            xn[0] = St; xn[1] = It; xn[2] = Rt;
            g_I[(t + 1) & 1][b][row] = It;

            const size_t ov = ((size_t)(b * TT + t) * NN + row) * 3;
            __stcs(out_view + ov,     St);
            __stcs(out_view + ov + 1, It);
            __stcs(out_view + ov + 2, Rt);
        }

        // ---------- phase 4: publish state, arrive ----------
        __syncthreads();
        if (t < TT - 1 && tid == 0) {
            __threadfence();                      // release
            atomicAdd(&g_arrive[b * TT + t], 1u);
        }
    }
}

// ---------------------------------------------------------------------------
// Launch
// ---------------------------------------------------------------------------
extern "C" void kernel_launch(void* const* d_in, const int* in_sizes, int n_in,
                              void* d_out, int out_size) {
    const float* x0;
    const float* params;
    if (in_sizes[0] == BQ * NN * 3) {
        x0     = (const float*)d_in[0];
        params = (const float*)d_in[1];
    } else {
        x0     = (const float*)d_in[1];
        params = (const float*)d_in[0];
    }

    float* out      = (float*)d_out;
    float* out_view = out;                              // (B,T,N,3)
    float* epi      = out + (size_t)BQ * TT * NN * 3;   // (B,T,N,514)

    reset_kernel<<<1, BQ * TT>>>();
    fused_kernel<<<BQ * BLOCKS_PER_BATCH, 256>>>(x0, params, out_view, epi);
}

// round 5
// speedup vs baseline: 1.9605x; 1.2010x over previous
#include <cuda_runtime.h>

// Problem shape (fixed by setup_inputs)
#define BQ 4
#define TT 96
#define NN 512
#define ROW_LEN 514              // [beta_logit, gamma_logit, z_0..z_511]
#define EPSV 1e-8f
#define BLKS_PER_BATCH 37        // 148 = 4 * 37 -> exactly 1 block per SM
#define GRID (BQ * BLKS_PER_BATCH)

// Scratch (allocations forbidden): ping-pong I vector + per-(b,t) barrier counters.
// S,I,R state lives in lane-0 registers (each warp owns its row for all t).
__device__ float    g_I[2][BQ][NN];
__device__ unsigned g_arrive[BQ * TT];

__global__ void reset_kernel() { g_arrive[threadIdx.x] = 0u; }

// ---------------------------------------------------------------------------
// Fused persistent kernel, 148 blocks x 512 threads (1 block/SM, balanced).
// Warp-per-row; rows [jloc*512/37, (jloc+1)*512/37) of batch b = blk/37.
// Per step t:
//   0) issue prefetch loads of params(t+1) into regs  (in flight all step)
//   1) softmax/sigmoid on regs(t) -> epi stores; c-row stays in regs
//   2) per-batch barrier wait(t-1)  [overlapped by the prefetch traffic]
//   3) I(t-1) -> smem; dot from regs; SIR update in lane-0 regs; outputs
//   4) release fence + arrive
// ---------------------------------------------------------------------------
__global__ __launch_bounds__(512, 1)
void fused_kernel(const float* __restrict__ x0,
                  const float* __restrict__ params,
                  float* __restrict__ out_view,
                  float* __restrict__ epi) {
    const int blk      = blockIdx.x;
    const int b        = blk / BLKS_PER_BATCH;
    const int jloc     = blk - b * BLKS_PER_BATCH;
    const int rowStart = (jloc * NN) / BLKS_PER_BATCH;
    const int rowEnd   = ((jloc + 1) * NN) / BLKS_PER_BATCH;
    const int tid  = threadIdx.x;
    const int lane = tid & 31;
    const int wid  = tid >> 5;               // 16 warps, up to 14 active
    const int row  = rowStart + wid;
    const bool active = (row < rowEnd);

    __shared__ float I_sh[NN];

    // Persistent SIR state in lane-0 registers
    float S = 0.f, I = 0.f, R = 0.f;
    if (active && lane == 0) {
        const float* xr = x0 + (size_t)(b * NN + row) * 3;
        S = xr[0]; I = xr[1]; R = xr[2];
    }

    // Prologue: load params(t=0). Rows are 8B-aligned -> float2 traffic.
    float2 z[8]; float bg = 0.f;
    if (active) {
        const float* p = params + ((size_t)(b * TT) * NN + row) * ROW_LEN;
        const float2* p2 = (const float2*)(p + 2);
#pragma unroll
        for (int k = 0; k < 8; k++) z[k] = __ldcs(p2 + lane + 32 * k);
        if (lane < 2) bg = __ldcs(p + lane);
    }

#pragma unroll 2
    for (int t = 0; t < TT; t++) {
        // ---- 0) prefetch params(t+1): 16 lines/warp in flight all step ----
        float2 zn[8]; float bgn = 0.f;
        if (active && t + 1 < TT) {
            const float* pn = params + ((size_t)(b * TT + t + 1) * NN + row) * ROW_LEN;
            const float2* pn2 = (const float2*)(pn + 2);
#pragma unroll
            for (int k = 0; k < 8; k++) zn[k] = __ldcs(pn2 + lane + 32 * k);
            if (lane < 2) bgn = __ldcs(pn + lane);
        }

        // ---- 1) sigmoid + softmax from registers ----
        float beta = 0.f, gamma = 0.f;
        if (active) {
            float mx = -3.4e38f;
#pragma unroll
            for (int k = 0; k < 8; k++) mx = fmaxf(mx, fmaxf(z[k].x, z[k].y));
#pragma unroll
            for (int off = 16; off; off >>= 1)
                mx = fmaxf(mx, __shfl_xor_sync(0xffffffffu, mx, off));

            float s = 0.f;
#pragma unroll
            for (int k = 0; k < 8; k++) {
                z[k].x = __expf(z[k].x - mx);
                z[k].y = __expf(z[k].y - mx);
                s += z[k].x + z[k].y;
            }
#pragma unroll
            for (int off = 16; off; off >>= 1)
                s += __shfl_xor_sync(0xffffffffu, s, off);
            const float inv = 1.0f / s;

            const size_t rbase = ((size_t)(b * TT + t) * NN + row) * ROW_LEN;
            float* o = epi + rbase;
            float sb = 0.f;
            if (lane < 2) {
                sb = 1.0f / (1.0f + __expf(-bg));
                __stcs(o + lane, sb);
            }
            float2* o2 = (float2*)(o + 2);
#pragma unroll
            for (int k = 0; k < 8; k++) {
                z[k].x *= inv; z[k].y *= inv;      // c-row stays in regs
                __stcs(o2 + lane + 32 * k, z[k]);
            }
            beta  = __shfl_sync(0xffffffffu, sb, 0);
            gamma = __shfl_sync(0xffffffffu, sb, 1);
        }

        // ---- 2) wait for step t-1 (prefetch loads fly during the spin) ----
        if (t > 0) {
            if (tid == 0) {
                volatile unsigned* vf = g_arrive + (b * TT + t - 1);
                while (*vf < BLKS_PER_BATCH) { }
                __threadfence();                   // acquire
            }
            __syncthreads();                       // also guards I_sh reuse
        }

        // ---- load I(t-1) into shared ----
        if (t == 0) {
            for (int i = tid; i < NN; i += 512)
                I_sh[i] = x0[(b * NN + i) * 3 + 1];
        } else {
            if (tid < NN / 2) {
                const float2* Ij = (const float2*)&g_I[t & 1][b][0];
                ((float2*)I_sh)[tid] = __ldcg(Ij + tid);
            }
        }
        __syncthreads();

        // ---- 3) infection dot from registers + SIR update ----
        if (active) {
            const float2* I2 = (const float2*)I_sh;
            float acc = 0.f;
#pragma unroll
            for (int k = 0; k < 8; k++) {
                const float2 iv = I2[lane + 32 * k];
                acc = fmaf(z[k].x, iv.x, fmaf(z[k].y, iv.y, acc));
            }
#pragma unroll
            for (int off = 16; off; off >>= 1)
                acc += __shfl_xor_sync(0xffffffffu, acc, off);

            if (lane == 0) {
                const float Np = fmaxf(S + I + R, EPSV);
                const float dS = -(beta * S * acc) / Np;
                const float dR = gamma * I;
                const float dI = -dS - dR;
                float St = fmaxf(S + dS, 0.f);
                float It = fmaxf(I + dI, 0.f);
                float Rt = fmaxf(R + dR, 0.f);
                const float scale = Np / fmaxf(St + It + Rt, EPSV);
                S = St * scale; I = It * scale; R = Rt * scale;

                g_I[(t + 1) & 1][b][row] = I;

                const size_t ov = ((size_t)(b * TT + t) * NN + row) * 3;
                __stcs(out_view + ov,     S);
                __stcs(out_view + ov + 1, I);
                __stcs(out_view + ov + 2, R);
            }
        }

        // ---- 4) publish + arrive ----
        __syncthreads();
        if (t < TT - 1 && tid == 0) {
            __threadfence();                       // release
            atomicAdd(&g_arrive[b * TT + t], 1u);
        }

        // rotate prefetch buffer
#pragma unroll
        for (int k = 0; k < 8; k++) z[k] = zn[k];
        bg = bgn;
    }
}

// ---------------------------------------------------------------------------
// Launch
// ---------------------------------------------------------------------------
extern "C" void kernel_launch(void* const* d_in, const int* in_sizes, int n_in,
                              void* d_out, int out_size) {
    const float* x0;
    const float* params;
    if (in_sizes[0] == BQ * NN * 3) {
        x0     = (const float*)d_in[0];
        params = (const float*)d_in[1];
    } else {
        x0     = (const float*)d_in[1];
        params = (const float*)d_in[0];
    }

    float* out      = (float*)d_out;
    float* out_view = out;                              // (B,T,N,3)
    float* epi      = out + (size_t)BQ * TT * NN * 3;   // (B,T,N,514)

    reset_kernel<<<1, BQ * TT>>>();
    fused_kernel<<<GRID, 512>>>(x0, params, out_view, epi);
}